// round 10
// baseline (speedup 1.0000x reference)
#include <cuda_runtime.h>
#include <cuda_bf16.h>
#include <math.h>

// Problem dims (fixed by the dataset)
#define B 32
#define S 2048
#define D 1024
#define K 10
#define NCHUNK 64              // s-chunks for partial mean (R8: 16 -> 64, isolated)
#define SCHUNK (S / NCHUNK)    // 32 rows per chunk
#define D4 (D / 4)             // 256 float4 per row

#define ALPHA_BASE 0.3f
#define MAX_DELTA 0.5f
#define EPS_WHITEN 1e-8f
#define EPS_NORM 1e-8f
#define EPS_FNORM 1e-12f

// Scratch (device globals -> no allocation)
__device__ float g_partial[B * NCHUNK * D];  // 8 MB
__device__ float g_vraw[B * D];              // 128 KB
__device__ float g_mean[D];                  // 4 KB
__device__ float g_rstd[D];                  // 4 KB
__device__ float g_corr[B * D];              // 128 KB

// ---------------------------------------------------------------------------
// Kernel 1: partial sums over sequence chunks. grid = (NCHUNK, B), 256 thr.
// Default-caching loads (ld.cs proven harmful in R3); larger grid for full
// occupancy during the read-only pass.
// ---------------------------------------------------------------------------
__global__ void k_partial(const float* __restrict__ h) {
    int chunk = blockIdx.x;
    int b = blockIdx.y;
    int t = threadIdx.x;  // 0..255 -> float4 index in D
    const float4* hp = reinterpret_cast<const float4*>(h)
                       + (size_t)(b * S + chunk * SCHUNK) * D4 + t;
    float ax = 0.f, ay = 0.f, az = 0.f, aw = 0.f;
#pragma unroll 8
    for (int s = 0; s < SCHUNK; s++) {
        float4 v = __ldg(hp + (size_t)s * D4);
        ax += v.x; ay += v.y; az += v.z; aw += v.w;
    }
    reinterpret_cast<float4*>(g_partial)[(b * NCHUNK + chunk) * D4 + t] =
        make_float4(ax, ay, az, aw);
}

// ---------------------------------------------------------------------------
// Kernel 2 (fused finalize + whitening stats). grid = 32 blocks, 256 thr.
// Warp w owns float4-column c; lane = batch. All traffic is L2-resident.
// ---------------------------------------------------------------------------
__device__ __forceinline__ float warp_allsum(float x) {
#pragma unroll
    for (int o = 16; o > 0; o >>= 1) x += __shfl_xor_sync(0xffffffffu, x, o);
    return x;
}

__global__ void k_stats(void) {
    int lane = threadIdx.x & 31;   // = batch b
    int w = threadIdx.x >> 5;      // 0..7
    int c = blockIdx.x * 8 + w;    // float4 column 0..255
    int b = lane;

    const float4* p4 = reinterpret_cast<const float4*>(g_partial);
    float ax = 0.f, ay = 0.f, az = 0.f, aw = 0.f;
#pragma unroll 8
    for (int ch = 0; ch < NCHUNK; ch++) {
        float4 v = p4[(b * NCHUNK + ch) * D4 + c];
        ax += v.x; ay += v.y; az += v.z; aw += v.w;
    }
    const float invS = 1.0f / (float)S;
    float4 vr = make_float4(ax * invS, ay * invS, az * invS, aw * invS);
    reinterpret_cast<float4*>(g_vraw)[b * D4 + c] = vr;

    // cross-batch mean / var (ddof=0) per component, via full-warp reduce
    const float invB = 1.0f / (float)B;
    float mx = warp_allsum(vr.x) * invB;
    float my = warp_allsum(vr.y) * invB;
    float mz = warp_allsum(vr.z) * invB;
    float mw = warp_allsum(vr.w) * invB;
    float qx = warp_allsum(vr.x * vr.x) * invB - mx * mx;
    float qy = warp_allsum(vr.y * vr.y) * invB - my * my;
    float qz = warp_allsum(vr.z * vr.z) * invB - mz * mz;
    float qw = warp_allsum(vr.w * vr.w) * invB - mw * mw;
    if (lane == 0) {
        reinterpret_cast<float4*>(g_mean)[c] = make_float4(mx, my, mz, mw);
        reinterpret_cast<float4*>(g_rstd)[c] =
            make_float4(rsqrtf(qx + EPS_WHITEN), rsqrtf(qy + EPS_WHITEN),
                        rsqrtf(qz + EPS_WHITEN), rsqrtf(qw + EPS_WHITEN));
    }
}

// ---------------------------------------------------------------------------
// Kernel 3: per-batch snap. grid = B, 256 threads. One fused 20-value block
// reduction; cos/argmax derived algebraically. (R7-proven)
// ---------------------------------------------------------------------------
__device__ __forceinline__ float warp_sum(float x) {
#pragma unroll
    for (int o = 16; o > 0; o >>= 1) x += __shfl_down_sync(0xffffffffu, x, o);
    return x;
}

__global__ void k_snap(const float* __restrict__ attractors) {
    __shared__ float red[2 * K][8];
    __shared__ float sums[2 * K];   // [0..K): ss1, [K..2K): dot
    __shared__ float alphaS, s1bS;
    __shared__ int bestIdxS;

    int b = blockIdx.x;
    int t = threadIdx.x;
    int lane = t & 31, wid = t >> 5;

    float4 vrb = reinterpret_cast<const float4*>(g_vraw)[b * D4 + t];
    float4 mean = reinterpret_cast<const float4*>(g_mean)[t];
    float4 rstd = reinterpret_cast<const float4*>(g_rstd)[t];
    float4 vn = make_float4((vrb.x - mean.x) * rstd.x, (vrb.y - mean.y) * rstd.y,
                            (vrb.z - mean.z) * rstd.z, (vrb.w - mean.w) * rstd.w);

    const float4* a4p = reinterpret_cast<const float4*>(attractors);
    float acc[2 * K];
#pragma unroll
    for (int k = 0; k < K; k++) {
        float4 a = __ldg(a4p + k * D4 + t);
        acc[k]     = a.x * a.x + a.y * a.y + a.z * a.z + a.w * a.w;
        acc[K + k] = vn.x * a.x + vn.y * a.y + vn.z * a.z + vn.w * a.w;
    }
#pragma unroll
    for (int j = 0; j < 2 * K; j++) {
        float x = warp_sum(acc[j]);
        if (lane == 0) red[j][wid] = x;
    }
    __syncthreads();
    if (t < 2 * K) {
        float s = 0.f;
#pragma unroll
        for (int j = 0; j < 8; j++) s += red[t][j];
        sums[t] = s;
    }
    __syncthreads();

    if (t == 0) {
        float best = -1e30f, s1b = 0.f;
        int bi = 0;
#pragma unroll
        for (int k = 0; k < K; k++) {
            float n1 = sqrtf(sums[k]);
            float s1 = 1.0f / fmaxf(n1, EPS_NORM);
            float n2 = n1 * s1;                       // ||att|| after first normalize
            float s2 = 1.0f / fmaxf(n2, EPS_FNORM);
            float cosk = sums[K + k] * s1 * s2;
            if (cosk > best) { best = cosk; bi = k; s1b = s1; }
        }
        bestIdxS = bi;
        s1bS = s1b;
        alphaS = ALPHA_BASE * (1.0f - best);
    }
    __syncthreads();

    float alpha = alphaS;
    float s1 = s1bS;
    float4 craw = __ldg(a4p + bestIdxS * D4 + t);
    float cx = craw.x * s1, cy = craw.y * s1, cz = craw.z * s1, cw = craw.w * s1;

    float dx = fminf(fmaxf(cx - vn.x, -MAX_DELTA), MAX_DELTA);
    float dy = fminf(fmaxf(cy - vn.y, -MAX_DELTA), MAX_DELTA);
    float dz = fminf(fmaxf(cz - vn.z, -MAX_DELTA), MAX_DELTA);
    float dw = fminf(fmaxf(cw - vn.w, -MAX_DELTA), MAX_DELTA);

    reinterpret_cast<float4*>(g_corr)[b * D4 + t] =
        make_float4(vn.x + alpha * dx - vrb.x,
                    vn.y + alpha * dy - vrb.y,
                    vn.z + alpha * dz - vrb.z,
                    vn.w + alpha * dw - vrb.w);
}

// ---------------------------------------------------------------------------
// Kernel 4: out = hidden + correction[b][d]  — tiled burst RW (R6-proven).
// ---------------------------------------------------------------------------
__global__ void k_add(const float* __restrict__ h, float* __restrict__ out) {
    const float4* __restrict__ h4 = reinterpret_cast<const float4*>(h);
    float4* __restrict__ o4 = reinterpret_cast<float4*>(out);
    const float4* __restrict__ c4 = reinterpret_cast<const float4*>(g_corr);
    const int ntiles = (B * S * D4) / 1024;  // 16384
    const int t = threadIdx.x;               // 0..255 == column id
    for (int tile = blockIdx.x; tile < ntiles; tile += gridDim.x) {
        int b = tile >> 9;  // 512 tiles per batch
        const float4* hp = h4 + (size_t)tile * 1024 + t;
        float4* op = o4 + (size_t)tile * 1024 + t;
        float4 c = __ldg(c4 + (b << 8) + t);
        float4 v0 = __ldg(hp);
        float4 v1 = __ldg(hp + 256);
        float4 v2 = __ldg(hp + 512);
        float4 v3 = __ldg(hp + 768);
        op[0]   = make_float4(v0.x + c.x, v0.y + c.y, v0.z + c.z, v0.w + c.w);
        op[256] = make_float4(v1.x + c.x, v1.y + c.y, v1.z + c.z, v1.w + c.w);
        op[512] = make_float4(v2.x + c.x, v2.y + c.y, v2.z + c.z, v2.w + c.w);
        op[768] = make_float4(v3.x + c.x, v3.y + c.y, v3.z + c.z, v3.w + c.w);
    }
}

// ---------------------------------------------------------------------------
extern "C" void kernel_launch(void* const* d_in, const int* in_sizes, int n_in,
                              void* d_out, int out_size) {
    const float* hidden = (const float*)d_in[0];      // [B, S, D]
    const float* attractors = (const float*)d_in[1];  // [K, D]
    float* out = (float*)d_out;
    (void)in_sizes; (void)n_in; (void)out_size;

    dim3 g1(NCHUNK, B);
    k_partial<<<g1, 256>>>(hidden);
    k_stats<<<32, 256>>>();
    k_snap<<<B, 256>>>(attractors);
    k_add<<<2048, 256>>>(hidden, out);
}

// round 12
// speedup vs baseline: 1.0669x; 1.0669x over previous
#include <cuda_runtime.h>
#include <cuda_bf16.h>
#include <math.h>

// Problem dims (fixed by the dataset)
#define B 32
#define S 2048
#define D 1024
#define K 10
#define NCHUNK 64              // s-chunks for partial mean
#define SCHUNK (S / NCHUNK)    // 32 rows per chunk
#define D4 (D / 4)             // 256 float4 per row

#define ALPHA_BASE 0.3f
#define MAX_DELTA 0.5f
#define EPS_WHITEN 1e-8f
#define EPS_NORM 1e-8f
#define EPS_FNORM 1e-12f

// Scratch (device globals -> no allocation)
__device__ float g_partial[B * NCHUNK * D];  // 8 MB
__device__ float g_vraw[B * D];              // 128 KB
__device__ float g_mean[D];                  // 4 KB
__device__ float g_rstd[D];                  // 4 KB
__device__ float g_corr[B * D];              // 128 KB

// ---------------------------------------------------------------------------
// Kernel 1: partial sums over sequence chunks. grid = (NCHUNK, B) = 2048 CTAs,
// 256 thr. Default-caching loads. Larger grid -> ~8 CTAs/SM during the pure
// read pass (isolated occupancy test; k_stats cost held constant this time).
// ---------------------------------------------------------------------------
__global__ void k_partial(const float* __restrict__ h) {
    int chunk = blockIdx.x;
    int b = blockIdx.y;
    int t = threadIdx.x;  // 0..255 -> float4 index in D
    const float4* hp = reinterpret_cast<const float4*>(h)
                       + (size_t)(b * S + chunk * SCHUNK) * D4 + t;
    float ax = 0.f, ay = 0.f, az = 0.f, aw = 0.f;
#pragma unroll 8
    for (int s = 0; s < SCHUNK; s++) {
        float4 v = __ldg(hp + (size_t)s * D4);
        ax += v.x; ay += v.y; az += v.z; aw += v.w;
    }
    reinterpret_cast<float4*>(g_partial)[(b * NCHUNK + chunk) * D4 + t] =
        make_float4(ax, ay, az, aw);
}

// ---------------------------------------------------------------------------
// Kernel 2 (finalize + whitening stats), scaled for NCHUNK=64.
// grid = 256 blocks (one float4 column c each), 256 thr (8 warps).
// Warp w covers chunks [8w, 8w+8); lane = batch. Shared-mem combine across
// warps, then full-warp shuffle reduce across batches for mean/var.
// ---------------------------------------------------------------------------
__device__ __forceinline__ float warp_allsum(float x) {
#pragma unroll
    for (int o = 16; o > 0; o >>= 1) x += __shfl_xor_sync(0xffffffffu, x, o);
    return x;
}

__global__ void k_stats(void) {
    __shared__ float4 part[8][32];
    int c = blockIdx.x;            // float4 column 0..255
    int lane = threadIdx.x & 31;   // = batch b
    int w = threadIdx.x >> 5;      // chunk group 0..7
    int b = lane;

    const float4* p4 = reinterpret_cast<const float4*>(g_partial);
    float ax = 0.f, ay = 0.f, az = 0.f, aw = 0.f;
#pragma unroll
    for (int j = 0; j < 8; j++) {
        int ch = w * 8 + j;
        float4 v = p4[(size_t)(b * NCHUNK + ch) * D4 + c];
        ax += v.x; ay += v.y; az += v.z; aw += v.w;
    }
    part[w][lane] = make_float4(ax, ay, az, aw);
    __syncthreads();

    if (w == 0) {
        float4 s = part[0][lane];
#pragma unroll
        for (int j = 1; j < 8; j++) {
            float4 v = part[j][lane];
            s.x += v.x; s.y += v.y; s.z += v.z; s.w += v.w;
        }
        const float invS = 1.0f / (float)S;
        float4 vr = make_float4(s.x * invS, s.y * invS, s.z * invS, s.w * invS);
        reinterpret_cast<float4*>(g_vraw)[b * D4 + c] = vr;

        const float invB = 1.0f / (float)B;
        float mx = warp_allsum(vr.x) * invB;
        float my = warp_allsum(vr.y) * invB;
        float mz = warp_allsum(vr.z) * invB;
        float mw = warp_allsum(vr.w) * invB;
        float qx = warp_allsum(vr.x * vr.x) * invB - mx * mx;
        float qy = warp_allsum(vr.y * vr.y) * invB - my * my;
        float qz = warp_allsum(vr.z * vr.z) * invB - mz * mz;
        float qw = warp_allsum(vr.w * vr.w) * invB - mw * mw;
        if (lane == 0) {
            reinterpret_cast<float4*>(g_mean)[c] = make_float4(mx, my, mz, mw);
            reinterpret_cast<float4*>(g_rstd)[c] =
                make_float4(rsqrtf(qx + EPS_WHITEN), rsqrtf(qy + EPS_WHITEN),
                            rsqrtf(qz + EPS_WHITEN), rsqrtf(qw + EPS_WHITEN));
        }
    }
}

// ---------------------------------------------------------------------------
// Kernel 3: per-batch snap. grid = B, 256 threads. One fused 20-value block
// reduction; cos/argmax derived algebraically. (R7-proven, unchanged)
// ---------------------------------------------------------------------------
__device__ __forceinline__ float warp_sum(float x) {
#pragma unroll
    for (int o = 16; o > 0; o >>= 1) x += __shfl_down_sync(0xffffffffu, x, o);
    return x;
}

__global__ void k_snap(const float* __restrict__ attractors) {
    __shared__ float red[2 * K][8];
    __shared__ float sums[2 * K];   // [0..K): ss1, [K..2K): dot
    __shared__ float alphaS, s1bS;
    __shared__ int bestIdxS;

    int b = blockIdx.x;
    int t = threadIdx.x;
    int lane = t & 31, wid = t >> 5;

    float4 vrb = reinterpret_cast<const float4*>(g_vraw)[b * D4 + t];
    float4 mean = reinterpret_cast<const float4*>(g_mean)[t];
    float4 rstd = reinterpret_cast<const float4*>(g_rstd)[t];
    float4 vn = make_float4((vrb.x - mean.x) * rstd.x, (vrb.y - mean.y) * rstd.y,
                            (vrb.z - mean.z) * rstd.z, (vrb.w - mean.w) * rstd.w);

    const float4* a4p = reinterpret_cast<const float4*>(attractors);
    float acc[2 * K];
#pragma unroll
    for (int k = 0; k < K; k++) {
        float4 a = __ldg(a4p + k * D4 + t);
        acc[k]     = a.x * a.x + a.y * a.y + a.z * a.z + a.w * a.w;
        acc[K + k] = vn.x * a.x + vn.y * a.y + vn.z * a.z + vn.w * a.w;
    }
#pragma unroll
    for (int j = 0; j < 2 * K; j++) {
        float x = warp_sum(acc[j]);
        if (lane == 0) red[j][wid] = x;
    }
    __syncthreads();
    if (t < 2 * K) {
        float s = 0.f;
#pragma unroll
        for (int j = 0; j < 8; j++) s += red[t][j];
        sums[t] = s;
    }
    __syncthreads();

    if (t == 0) {
        float best = -1e30f, s1b = 0.f;
        int bi = 0;
#pragma unroll
        for (int k = 0; k < K; k++) {
            float n1 = sqrtf(sums[k]);
            float s1 = 1.0f / fmaxf(n1, EPS_NORM);
            float n2 = n1 * s1;                       // ||att|| after first normalize
            float s2 = 1.0f / fmaxf(n2, EPS_FNORM);
            float cosk = sums[K + k] * s1 * s2;
            if (cosk > best) { best = cosk; bi = k; s1b = s1; }
        }
        bestIdxS = bi;
        s1bS = s1b;
        alphaS = ALPHA_BASE * (1.0f - best);
    }
    __syncthreads();

    float alpha = alphaS;
    float s1 = s1bS;
    float4 craw = __ldg(a4p + bestIdxS * D4 + t);
    float cx = craw.x * s1, cy = craw.y * s1, cz = craw.z * s1, cw = craw.w * s1;

    float dx = fminf(fmaxf(cx - vn.x, -MAX_DELTA), MAX_DELTA);
    float dy = fminf(fmaxf(cy - vn.y, -MAX_DELTA), MAX_DELTA);
    float dz = fminf(fmaxf(cz - vn.z, -MAX_DELTA), MAX_DELTA);
    float dw = fminf(fmaxf(cw - vn.w, -MAX_DELTA), MAX_DELTA);

    reinterpret_cast<float4*>(g_corr)[b * D4 + t] =
        make_float4(vn.x + alpha * dx - vrb.x,
                    vn.y + alpha * dy - vrb.y,
                    vn.z + alpha * dz - vrb.z,
                    vn.w + alpha * dw - vrb.w);
}

// ---------------------------------------------------------------------------
// Kernel 4: out = hidden + correction[b][d]  — tiled burst RW (R6-proven).
// ---------------------------------------------------------------------------
__global__ void k_add(const float* __restrict__ h, float* __restrict__ out) {
    const float4* __restrict__ h4 = reinterpret_cast<const float4*>(h);
    float4* __restrict__ o4 = reinterpret_cast<float4*>(out);
    const float4* __restrict__ c4 = reinterpret_cast<const float4*>(g_corr);
    const int ntiles = (B * S * D4) / 1024;  // 16384
    const int t = threadIdx.x;               // 0..255 == column id
    for (int tile = blockIdx.x; tile < ntiles; tile += gridDim.x) {
        int b = tile >> 9;  // 512 tiles per batch
        const float4* hp = h4 + (size_t)tile * 1024 + t;
        float4* op = o4 + (size_t)tile * 1024 + t;
        float4 c = __ldg(c4 + (b << 8) + t);
        float4 v0 = __ldg(hp);
        float4 v1 = __ldg(hp + 256);
        float4 v2 = __ldg(hp + 512);
        float4 v3 = __ldg(hp + 768);
        op[0]   = make_float4(v0.x + c.x, v0.y + c.y, v0.z + c.z, v0.w + c.w);
        op[256] = make_float4(v1.x + c.x, v1.y + c.y, v1.z + c.z, v1.w + c.w);
        op[512] = make_float4(v2.x + c.x, v2.y + c.y, v2.z + c.z, v2.w + c.w);
        op[768] = make_float4(v3.x + c.x, v3.y + c.y, v3.z + c.z, v3.w + c.w);
    }
}

// ---------------------------------------------------------------------------
extern "C" void kernel_launch(void* const* d_in, const int* in_sizes, int n_in,
                              void* d_out, int out_size) {
    const float* hidden = (const float*)d_in[0];      // [B, S, D]
    const float* attractors = (const float*)d_in[1];  // [K, D]
    float* out = (float*)d_out;
    (void)in_sizes; (void)n_in; (void)out_size;

    dim3 g1(NCHUNK, B);
    k_partial<<<g1, 256>>>(hidden);
    k_stats<<<256, 256>>>();
    k_snap<<<B, 256>>>(attractors);
    k_add<<<2048, 256>>>(hidden, out);
}